// round 3
// baseline (speedup 1.0000x reference)
#include <cuda_runtime.h>

#define MAXN 100000
#define MAXE 1600000

// Scratch (static __device__ arrays — no allocation allowed).
// g_h1/g_h2 hold dinv-prescaled features (gather source, read-only during agg).
// g_agg1/g_agg2 are initialized by the GEMMs to the same value (self-loop term)
// and accumulated into by the edge kernels.
__device__ __align__(256) float g_h1[MAXN * 64];
__device__ __align__(256) float g_agg1[MAXN * 64];
__device__ __align__(256) float g_h2[MAXN * 48];    // padded 41->48
__device__ __align__(256) float g_agg2[MAXN * 48];
__device__ int   g_deg[MAXN];
__device__ float g_dinv[MAXN];

// ---------------------------------------------------------------------------
// Degree / normalization
// ---------------------------------------------------------------------------
__global__ void k_deg_init(int n) {
    int i = blockIdx.x * blockDim.x + threadIdx.x;
    if (i < n) g_deg[i] = 1;  // self-loop
}

__global__ void k_deg_count(const int* __restrict__ dst, int E) {
    int e = blockIdx.x * blockDim.x + threadIdx.x;
    if (e < E) atomicAdd(&g_deg[dst[e]], 1);
}

__global__ void k_dinv(int n) {
    int i = blockIdx.x * blockDim.x + threadIdx.x;
    if (i < n) g_dinv[i] = rsqrtf((float)g_deg[i]);
}

// ---------------------------------------------------------------------------
// GEMM1: hs1[n,64] = dinv[row] * (x[n,128] @ W1[128,64])
// 64x64 block tile, 4x4 register tile per thread, K split into two 64-tiles.
// Writes result to BOTH g_h1 (gather src) and g_agg1 (self-loop init).
// ---------------------------------------------------------------------------
__global__ __launch_bounds__(256) void k_gemm1(const float* __restrict__ x,
                                               const float* __restrict__ W,
                                               int n) {
    __shared__ float ws[64][64];  // W1 k-tile, [k][col]   16 KB
    __shared__ float xs[64][68];  // x tile transposed [k][row], padded
    int tid = threadIdx.x;
    int tx = tid & 15;            // col group: cols 4*tx .. 4*tx+3
    int ty = tid >> 4;            // row group: rows 4*ty .. 4*ty+3
    int c0 = tx * 4;
    int rr = ty * 4;
    int r0 = blockIdx.x * 64;

    float acc[4][4] = {};

    for (int kt = 0; kt < 2; kt++) {
        for (int i = tid; i < 64 * 64; i += 256) {
            int k = i >> 6, c = i & 63;
            ws[k][c] = W[(kt * 64 + k) * 64 + c];
        }
        for (int i = tid; i < 64 * 64; i += 256) {
            int r = i >> 6, c = i & 63;
            float v = (r0 + r < n) ? x[(r0 + r) * 128 + kt * 64 + c] : 0.f;
            xs[c][r] = v;
        }
        __syncthreads();

#pragma unroll 4
        for (int k = 0; k < 64; k++) {
            float4 wv = *(const float4*)&ws[k][c0];
            float4 xv = *(const float4*)&xs[k][rr];
            acc[0][0] += xv.x * wv.x; acc[0][1] += xv.x * wv.y;
            acc[0][2] += xv.x * wv.z; acc[0][3] += xv.x * wv.w;
            acc[1][0] += xv.y * wv.x; acc[1][1] += xv.y * wv.y;
            acc[1][2] += xv.y * wv.z; acc[1][3] += xv.y * wv.w;
            acc[2][0] += xv.z * wv.x; acc[2][1] += xv.z * wv.y;
            acc[2][2] += xv.z * wv.z; acc[2][3] += xv.z * wv.w;
            acc[3][0] += xv.w * wv.x; acc[3][1] += xv.w * wv.y;
            acc[3][2] += xv.w * wv.z; acc[3][3] += xv.w * wv.w;
        }
        __syncthreads();
    }

#pragma unroll
    for (int i = 0; i < 4; i++) {
        int row = r0 + rr + i;
        if (row < n) {
            float di = g_dinv[row];
            float4 o = make_float4(acc[i][0] * di, acc[i][1] * di,
                                   acc[i][2] * di, acc[i][3] * di);
            *(float4*)&g_h1[row * 64 + c0]   = o;
            *(float4*)&g_agg1[row * 64 + c0] = o;
        }
    }
}

// ---------------------------------------------------------------------------
// Vectorized no-return global reduction (sm_90+)
// ---------------------------------------------------------------------------
__device__ __forceinline__ void red4(float4* p, float4 v) {
    asm volatile("red.global.add.v4.f32 [%0], {%1, %2, %3, %4};"
                 :: "l"(p), "f"(v.x), "f"(v.y), "f"(v.z), "f"(v.w)
                 : "memory");
}

// ---------------------------------------------------------------------------
// Layer-1 edge aggregation: 8 threads/edge, TWO float4 each (j and j+8).
// No arithmetic — features pre-scaled; dinv[d] applied downstream.
// ---------------------------------------------------------------------------
__global__ __launch_bounds__(256) void k_agg1(const int* __restrict__ src,
                                              const int* __restrict__ dst,
                                              int E) {
    int g = blockIdx.x * blockDim.x + threadIdx.x;
    int e = g >> 3;
    if (e >= E) return;
    int j = g & 7;
    int s = src[e], d = dst[e];
    const float4* hp = (const float4*)g_h1 + s * 16 + j;
    float4* ap = (float4*)g_agg1 + d * 16 + j;
    float4 v0 = hp[0];
    float4 v1 = hp[8];
    red4(ap,     v0);
    red4(ap + 8, v1);
}

// ---------------------------------------------------------------------------
// GEMM2: hs2[n,48] = dinv[row] * (relu_fused(agg1)[n,64] @ W2pad[64,48])
// ReLU/bias/dinv epilogue of layer 1 is fused into the operand load.
// 64x48 block tile, 4x4 register tile, 192 threads. Writes g_h2 and g_agg2.
// ---------------------------------------------------------------------------
__global__ __launch_bounds__(192) void k_gemm2(const float* __restrict__ W2,
                                               const float* __restrict__ b1,
                                               int n) {
    __shared__ float ws[64][48];  // 12 KB
    __shared__ float xs[64][68];  // transposed [k][row]
    int tid = threadIdx.x;
    int tx = tid % 12;            // col group
    int ty = tid / 12;            // row group
    int c0 = tx * 4;
    int rr = ty * 4;
    int r0 = blockIdx.x * 64;

    for (int i = tid; i < 64 * 48; i += 192) {
        int k = i / 48, c = i - k * 48;
        ws[k][c] = (c < 41) ? W2[k * 41 + c] : 0.f;
    }
    // Fused layer-1 epilogue: x = relu(dinv[r]*agg1 + b1[c])
    for (int i = tid; i < 64 * 64; i += 192) {
        int r = i >> 6, c = i & 63;
        float v = 0.f;
        int row = r0 + r;
        if (row < n)
            v = fmaxf(fmaf(g_dinv[row], g_agg1[row * 64 + c], b1[c]), 0.f);
        xs[c][r] = v;
    }
    __syncthreads();

    float acc[4][4] = {};
#pragma unroll 4
    for (int k = 0; k < 64; k++) {
        float4 wv = *(const float4*)&ws[k][c0];
        float4 xv = *(const float4*)&xs[k][rr];
        acc[0][0] += xv.x * wv.x; acc[0][1] += xv.x * wv.y;
        acc[0][2] += xv.x * wv.z; acc[0][3] += xv.x * wv.w;
        acc[1][0] += xv.y * wv.x; acc[1][1] += xv.y * wv.y;
        acc[1][2] += xv.y * wv.z; acc[1][3] += xv.y * wv.w;
        acc[2][0] += xv.z * wv.x; acc[2][1] += xv.z * wv.y;
        acc[2][2] += xv.z * wv.z; acc[2][3] += xv.z * wv.w;
        acc[3][0] += xv.w * wv.x; acc[3][1] += xv.w * wv.y;
        acc[3][2] += xv.w * wv.z; acc[3][3] += xv.w * wv.w;
    }

#pragma unroll
    for (int i = 0; i < 4; i++) {
        int row = r0 + rr + i;
        if (row < n) {
            float di = g_dinv[row];
            float4 o = make_float4(acc[i][0] * di, acc[i][1] * di,
                                   acc[i][2] * di, acc[i][3] * di);
            *(float4*)&g_h2[row * 48 + c0]   = o;
            *(float4*)&g_agg2[row * 48 + c0] = o;
        }
    }
}

// ---------------------------------------------------------------------------
// Layer-2 edge aggregation: 6 threads/edge, TWO float4 each (j and j+6).
// ---------------------------------------------------------------------------
__global__ __launch_bounds__(256) void k_agg2(const int* __restrict__ src,
                                              const int* __restrict__ dst,
                                              int E) {
    int g = blockIdx.x * blockDim.x + threadIdx.x;
    int e = g / 6;
    if (e >= E) return;
    int j = g - e * 6;
    int s = src[e], d = dst[e];
    const float4* hp = (const float4*)g_h2 + s * 12 + j;
    float4* ap = (float4*)g_agg2 + d * 12 + j;
    float4 v0 = hp[0];
    float4 v1 = hp[6];
    red4(ap,     v0);
    red4(ap + 6, v1);
}

// ---------------------------------------------------------------------------
// Epilogue 2: out = dinv[v]*agg + b2, unpad 48 -> 41.
// ---------------------------------------------------------------------------
__global__ void k_post2(const float* __restrict__ b2, float* __restrict__ out,
                        int n) {
    int idx = blockIdx.x * blockDim.x + threadIdx.x;
    if (idx >= n * 41) return;
    int v = idx / 41;
    int c = idx - v * 41;
    out[idx] = fmaf(g_dinv[v], g_agg2[v * 48 + c], b2[c]);
}

// ---------------------------------------------------------------------------
extern "C" void kernel_launch(void* const* d_in, const int* in_sizes, int n_in,
                              void* d_out, int out_size) {
    const float* x  = (const float*)d_in[0];
    const int*   ei = (const int*)d_in[1];
    const float* W1 = (const float*)d_in[2];
    const float* b1 = (const float*)d_in[3];
    const float* W2 = (const float*)d_in[4];
    const float* b2 = (const float*)d_in[5];
    float* out = (float*)d_out;

    int n = in_sizes[0] / 128;
    int E = in_sizes[1] / 2;
    const int* src = ei;
    const int* dst = ei + E;

    k_deg_init<<<(n + 255) / 256, 256>>>(n);
    k_deg_count<<<(E + 255) / 256, 256>>>(dst, E);
    k_dinv<<<(n + 255) / 256, 256>>>(n);

    k_gemm1<<<(n + 63) / 64, 256>>>(x, W1, n);

    long long t1 = (long long)E * 8;
    k_agg1<<<(int)((t1 + 255) / 256), 256>>>(src, dst, E);

    k_gemm2<<<(n + 63) / 64, 192>>>(W2, b1, n);

    long long t2 = (long long)E * 6;
    k_agg2<<<(int)((t2 + 255) / 256), 256>>>(src, dst, E);

    k_post2<<<(n * 41 + 255) / 256, 256>>>(b2, out, n);
}

// round 7
// speedup vs baseline: 1.4020x; 1.4020x over previous
#include <cuda_runtime.h>

#define MAXN 100000
#define MAXE 1600000
#define SCAN_BLK 512
#define NBLK_MAX ((MAXN + SCAN_BLK - 1) / SCAN_BLK)

// Scratch (static __device__ arrays — no allocation allowed).
__device__ __align__(256) float g_h1[MAXN * 64];   // dinv-prescaled x@W1
__device__ __align__(256) float g_hr[MAXN * 64];   // relu layer-1 out (gemm2 input)
__device__ __align__(256) float g_h2[MAXN * 48];   // dinv-prescaled hr@W2, pad 41->48
__device__ int   g_indeg[MAXN];
__device__ float g_dinv[MAXN];
__device__ int   g_rowstart[MAXN + 1];
__device__ int   g_cursor[MAXN];
__device__ int   g_adj[MAXE];
__device__ int   g_bsum[NBLK_MAX];

// ---------------------------------------------------------------------------
// Degree / normalization
// ---------------------------------------------------------------------------
__global__ void k_zero_indeg(int n) {
    int i = blockIdx.x * blockDim.x + threadIdx.x;
    if (i < n) g_indeg[i] = 0;
}

__global__ void k_count(const int* __restrict__ dst, int E) {
    int e = blockIdx.x * blockDim.x + threadIdx.x;
    if (e < E) atomicAdd(&g_indeg[dst[e]], 1);
}

__global__ void k_dinv(int n) {
    int i = blockIdx.x * blockDim.x + threadIdx.x;
    if (i < n) g_dinv[i] = rsqrtf((float)(g_indeg[i] + 1));  // +1 self-loop
}

// ---------------------------------------------------------------------------
// Exclusive scan of indeg -> rowstart (CSR offsets). 3-kernel two-level scan.
// ---------------------------------------------------------------------------
__global__ __launch_bounds__(SCAN_BLK) void k_scan1(int n) {
    __shared__ int s[SCAN_BLK];
    int i = blockIdx.x * SCAN_BLK + threadIdx.x;
    int v = (i < n) ? g_indeg[i] : 0;
    s[threadIdx.x] = v;
    __syncthreads();
    for (int off = 1; off < SCAN_BLK; off <<= 1) {
        int add = (threadIdx.x >= off) ? s[threadIdx.x - off] : 0;
        __syncthreads();
        s[threadIdx.x] += add;
        __syncthreads();
    }
    int incl = s[threadIdx.x];
    if (i < n) g_rowstart[i] = incl - v;  // block-local exclusive
    if (threadIdx.x == SCAN_BLK - 1) g_bsum[blockIdx.x] = incl;
}

__global__ __launch_bounds__(256) void k_scan2(int nb) {
    __shared__ int s[256];
    int v = (threadIdx.x < nb) ? g_bsum[threadIdx.x] : 0;
    s[threadIdx.x] = v;
    __syncthreads();
    for (int off = 1; off < 256; off <<= 1) {
        int add = (threadIdx.x >= off) ? s[threadIdx.x - off] : 0;
        __syncthreads();
        s[threadIdx.x] += add;
        __syncthreads();
    }
    if (threadIdx.x < nb) g_bsum[threadIdx.x] = s[threadIdx.x] - v;  // exclusive
}

__global__ void k_scan3(int n) {
    int i = blockIdx.x * blockDim.x + threadIdx.x;
    if (i >= n) return;
    int r = g_rowstart[i] + g_bsum[i / SCAN_BLK];
    g_rowstart[i] = r;
    g_cursor[i] = r;
    if (i == n - 1) g_rowstart[n] = r + g_indeg[i];
}

__global__ void k_fill(const int* __restrict__ src, const int* __restrict__ dst,
                       int E) {
    int e = blockIdx.x * blockDim.x + threadIdx.x;
    if (e >= E) return;
    int p = atomicAdd(&g_cursor[dst[e]], 1);
    g_adj[p] = src[e];
}

// ---------------------------------------------------------------------------
// GEMM1: g_h1[n,64] = dinv[row] * (x[n,128] @ W1[128,64])
// 128x64 block tile, 8x8 register tile, 128 threads, K in 4 tiles of 32.
// ---------------------------------------------------------------------------
__global__ __launch_bounds__(128) void k_gemm1(const float* __restrict__ x,
                                               const float* __restrict__ W,
                                               int n) {
    __shared__ float ws[32][64];    // 8 KB   [k][col]
    __shared__ float xs[32][132];   // 16.5KB [k][row], padded
    int tid = threadIdx.x;
    int tx = tid & 7;               // col group: cols 8*tx..+7
    int ty = tid >> 3;              // row group: rows 8*ty..+7
    int c0 = tx * 8, rr = ty * 8;
    int r0 = blockIdx.x * 128;

    float acc[8][8] = {};

    for (int kt = 0; kt < 4; kt++) {
        const float4* Wp = (const float4*)W + kt * 512;
#pragma unroll
        for (int i = 0; i < 4; i++)
            ((float4*)ws)[tid + i * 128] = Wp[tid + i * 128];
#pragma unroll
        for (int it = 0; it < 8; it++) {
            int i = tid + it * 128;           // 0..1023
            int f = i & 7, r = i >> 3;
            float4 v = make_float4(0.f, 0.f, 0.f, 0.f);
            if (r0 + r < n)
                v = *(const float4*)&x[(r0 + r) * 128 + kt * 32 + f * 4];
            xs[f * 4 + 0][r] = v.x;
            xs[f * 4 + 1][r] = v.y;
            xs[f * 4 + 2][r] = v.z;
            xs[f * 4 + 3][r] = v.w;
        }
        __syncthreads();

#pragma unroll
        for (int k = 0; k < 32; k++) {
            float4 w0 = *(const float4*)&ws[k][c0];
            float4 w1 = *(const float4*)&ws[k][c0 + 4];
            float4 x0 = *(const float4*)&xs[k][rr];
            float4 x1 = *(const float4*)&xs[k][rr + 4];
            float wv[8] = {w0.x, w0.y, w0.z, w0.w, w1.x, w1.y, w1.z, w1.w};
            float xv[8] = {x0.x, x0.y, x0.z, x0.w, x1.x, x1.y, x1.z, x1.w};
#pragma unroll
            for (int a = 0; a < 8; a++)
#pragma unroll
                for (int b = 0; b < 8; b++) acc[a][b] += xv[a] * wv[b];
        }
        __syncthreads();
    }

#pragma unroll
    for (int a = 0; a < 8; a++) {
        int row = r0 + rr + a;
        if (row < n) {
            float di = g_dinv[row];
            *(float4*)&g_h1[row * 64 + c0] =
                make_float4(acc[a][0] * di, acc[a][1] * di, acc[a][2] * di, acc[a][3] * di);
            *(float4*)&g_h1[row * 64 + c0 + 4] =
                make_float4(acc[a][4] * di, acc[a][5] * di, acc[a][6] * di, acc[a][7] * di);
        }
    }
}

// ---------------------------------------------------------------------------
// Gather 1: acc = h1[v] + sum_{s in N(v)} h1[s]; fused epilogue
// hr[v] = relu(dinv[v]*acc + b1). 16 threads/node, one float4 lane each.
// Neighbor loop 4-way unrolled for MLP.
// ---------------------------------------------------------------------------
__global__ __launch_bounds__(256) void k_gather1(const float* __restrict__ b1,
                                                 int n) {
    int g = blockIdx.x * blockDim.x + threadIdx.x;
    int v = g >> 4;
    if (v >= n) return;
    int j = g & 15;

    const float4* h4 = (const float4*)g_h1;
    float4 acc = h4[v * 16 + j];  // self-loop (prescaled)
    int p = g_rowstart[v], end = g_rowstart[v + 1];
    for (; p + 3 < end; p += 4) {
        int s0 = g_adj[p], s1 = g_adj[p + 1], s2 = g_adj[p + 2], s3 = g_adj[p + 3];
        float4 t0 = h4[s0 * 16 + j];
        float4 t1 = h4[s1 * 16 + j];
        float4 t2 = h4[s2 * 16 + j];
        float4 t3 = h4[s3 * 16 + j];
        acc.x += t0.x; acc.y += t0.y; acc.z += t0.z; acc.w += t0.w;
        acc.x += t1.x; acc.y += t1.y; acc.z += t1.z; acc.w += t1.w;
        acc.x += t2.x; acc.y += t2.y; acc.z += t2.z; acc.w += t2.w;
        acc.x += t3.x; acc.y += t3.y; acc.z += t3.z; acc.w += t3.w;
    }
    for (; p < end; p++) {
        float4 t = h4[g_adj[p] * 16 + j];
        acc.x += t.x; acc.y += t.y; acc.z += t.z; acc.w += t.w;
    }
    float di = g_dinv[v];
    float4 b = ((const float4*)b1)[j];
    acc.x = fmaxf(fmaf(di, acc.x, b.x), 0.f);
    acc.y = fmaxf(fmaf(di, acc.y, b.y), 0.f);
    acc.z = fmaxf(fmaf(di, acc.z, b.z), 0.f);
    acc.w = fmaxf(fmaf(di, acc.w, b.w), 0.f);
    ((float4*)g_hr)[v * 16 + j] = acc;
}

// ---------------------------------------------------------------------------
// GEMM2: g_h2[n,48] = dinv[row] * (hr[n,64] @ W2pad[64,48]); cols 41..47 = 0.
// 128x48 block tile, 8x8 register tile, 96 threads, K in 2 tiles of 32.
// ---------------------------------------------------------------------------
__global__ __launch_bounds__(96) void k_gemm2(const float* __restrict__ W2,
                                              int n) {
    __shared__ float ws[32][48];    // 6 KB
    __shared__ float xs[32][132];   // 16.5 KB
    int tid = threadIdx.x;
    int tx = tid % 6;               // col group: cols 8*tx..+7
    int ty = tid / 6;               // row group: rows 8*ty..+7
    int c0 = tx * 8, rr = ty * 8;
    int r0 = blockIdx.x * 128;

    float acc[8][8] = {};

    for (int kt = 0; kt < 2; kt++) {
        for (int i = tid; i < 32 * 48; i += 96) {
            int k = i / 48, c = i - k * 48;
            ws[k][c] = (c < 41) ? W2[(kt * 32 + k) * 41 + c] : 0.f;
        }
        for (int i = tid; i < 1024; i += 96) {
            int f = i & 7, r = i >> 3;
            float4 v = make_float4(0.f, 0.f, 0.f, 0.f);
            if (r0 + r < n)
                v = *(const float4*)&g_hr[(r0 + r) * 64 + kt * 32 + f * 4];
            xs[f * 4 + 0][r] = v.x;
            xs[f * 4 + 1][r] = v.y;
            xs[f * 4 + 2][r] = v.z;
            xs[f * 4 + 3][r] = v.w;
        }
        __syncthreads();

#pragma unroll
        for (int k = 0; k < 32; k++) {
            float4 w0 = *(const float4*)&ws[k][c0];
            float4 w1 = *(const float4*)&ws[k][c0 + 4];
            float4 x0 = *(const float4*)&xs[k][rr];
            float4 x1 = *(const float4*)&xs[k][rr + 4];
            float wv[8] = {w0.x, w0.y, w0.z, w0.w, w1.x, w1.y, w1.z, w1.w};
            float xv[8] = {x0.x, x0.y, x0.z, x0.w, x1.x, x1.y, x1.z, x1.w};
#pragma unroll
            for (int a = 0; a < 8; a++)
#pragma unroll
                for (int b = 0; b < 8; b++) acc[a][b] += xv[a] * wv[b];
        }
        __syncthreads();
    }

#pragma unroll
    for (int a = 0; a < 8; a++) {
        int row = r0 + rr + a;
        if (row < n) {
            float di = g_dinv[row];
            *(float4*)&g_h2[row * 48 + c0] =
                make_float4(acc[a][0] * di, acc[a][1] * di, acc[a][2] * di, acc[a][3] * di);
            *(float4*)&g_h2[row * 48 + c0 + 4] =
                make_float4(acc[a][4] * di, acc[a][5] * di, acc[a][6] * di, acc[a][7] * di);
        }
    }
}

// ---------------------------------------------------------------------------
// Gather 2 + fused epilogue: out[v,c] = dinv[v]*(h2[v]+sum h2[s]) + b2, c<41.
// 12 threads/node; lane 11 (pure padding cols 44..47) exits early.
// ---------------------------------------------------------------------------
__global__ __launch_bounds__(256) void k_gather2(const float* __restrict__ b2,
                                                 float* __restrict__ out,
                                                 int n) {
    int g = blockIdx.x * blockDim.x + threadIdx.x;
    int v = g / 12;
    if (v >= n) return;
    int j = g - v * 12;
    if (j == 11) return;  // cols 44..47 are padding

    const float4* h4 = (const float4*)g_h2;
    float4 acc = h4[v * 12 + j];  // self-loop
    int p = g_rowstart[v], end = g_rowstart[v + 1];
    for (; p + 3 < end; p += 4) {
        int s0 = g_adj[p], s1 = g_adj[p + 1], s2 = g_adj[p + 2], s3 = g_adj[p + 3];
        float4 t0 = h4[s0 * 12 + j];
        float4 t1 = h4[s1 * 12 + j];
        float4 t2 = h4[s2 * 12 + j];
        float4 t3 = h4[s3 * 12 + j];
        acc.x += t0.x; acc.y += t0.y; acc.z += t0.z; acc.w += t0.w;
        acc.x += t1.x; acc.y += t1.y; acc.z += t1.z; acc.w += t1.w;
        acc.x += t2.x; acc.y += t2.y; acc.z += t2.z; acc.w += t2.w;
        acc.x += t3.x; acc.y += t3.y; acc.z += t3.z; acc.w += t3.w;
    }
    for (; p < end; p++) {
        float4 t = h4[g_adj[p] * 12 + j];
        acc.x += t.x; acc.y += t.y; acc.z += t.z; acc.w += t.w;
    }
    float di = g_dinv[v];
    int c0 = j * 4;
    float r0v = fmaf(di, acc.x, b2[c0]);
    float* o = out + v * 41 + c0;
    if (j < 10) {
        o[0] = r0v;
        o[1] = fmaf(di, acc.y, b2[c0 + 1]);
        o[2] = fmaf(di, acc.z, b2[c0 + 2]);
        o[3] = fmaf(di, acc.w, b2[c0 + 3]);
    } else {
        o[0] = r0v;  // col 40 only
    }
}

// ---------------------------------------------------------------------------
extern "C" void kernel_launch(void* const* d_in, const int* in_sizes, int n_in,
                              void* d_out, int out_size) {
    const float* x  = (const float*)d_in[0];
    const int*   ei = (const int*)d_in[1];
    const float* W1 = (const float*)d_in[2];
    const float* b1 = (const float*)d_in[3];
    const float* W2 = (const float*)d_in[4];
    const float* b2 = (const float*)d_in[5];
    float* out = (float*)d_out;

    int n = in_sizes[0] / 128;
    int E = in_sizes[1] / 2;
    const int* src = ei;
    const int* dst = ei + E;
    int nb = (n + SCAN_BLK - 1) / SCAN_BLK;

    k_zero_indeg<<<(n + 255) / 256, 256>>>(n);
    k_count<<<(E + 255) / 256, 256>>>(dst, E);
    k_dinv<<<(n + 255) / 256, 256>>>(n);

    // GEMM1 depends only on dinv, not on the CSR chain.
    k_gemm1<<<(n + 127) / 128, 128>>>(x, W1, n);

    k_scan1<<<nb, SCAN_BLK>>>(n);
    k_scan2<<<1, 256>>>(nb);
    k_scan3<<<(n + 255) / 256, 256>>>(n);
    k_fill<<<(E + 255) / 256, 256>>>(src, dst, E);

    k_gather1<<<(n * 16 + 255) / 256, 256>>>(b1, n);

    k_gemm2<<<(n + 127) / 128, 96>>>(W2, n);

    k_gather2<<<(n * 12 + 255) / 256, 256>>>(b2, out, n);
}